// round 10
// baseline (speedup 1.0000x reference)
#include <cuda_runtime.h>
#include <cuda_bf16.h>
#include <cstdint>

// EvroModel: x[131072,256] -> relu(x@w1+b1)[.,64] -> tanh(@w2+b2)[.,16] -> @w3+b3 [.,4]
// -> softmax over the ENTIRE flattened tensor.
//
// Round 10: layer-1 GEMM moves from 3xTF32 (half-rate mma) to a 3-way bf16
// split on full-rate mma.sync.m16n8k16.bf16: x,w1 = h+m+l (bf16 levels),
// keep the 6 products with i+j<=2 (dropped terms ~2^-27 rel). Same MMA
// instruction count per unit k, each at 2x the MAC width and full rate
// -> tensor-pipe cycles halve. Epilogue/softmax unchanged.

#define B_ROWS   131072
#define ROWS_CTA 512
#define NBLK     (B_ROWS / ROWS_CTA)   // 256
#define TPB      512
#define KDIM     256
#define H1_PITCH 68

// byte offsets
#define SBHM_OFF_B 0                   // h+m frags: 16*8*8*4 cells * 16B = 65536
#define SBL_OFF_B  65536               // l frags:   same cells * 8B      = 32768
// float offsets (h1 aliases the B region after the GEMM)
#define H1_OFF_F   0                   // 512 x 68 floats = 139264 B
#define W2_OFF_F   34816               // 64 x 16
#define B1_OFF_F   35840               // 64
#define B2_OFF_F   35904               // 16
#define W3_OFF_F   35920               // 16 x 4
#define B3_OFF_F   35984               // 4
#define RED_OFF_F  35988               // 512
#define SM_FLOATS  36500

__device__ float g_partials[NBLK];

__device__ __forceinline__ uint32_t smem_u32(const void* p) {
    uint32_t a;
    asm("{ .reg .u64 t; cvta.to.shared.u64 t, %1; cvt.u32.u64 %0, t; }" : "=r"(a) : "l"(p));
    return a;
}
__device__ __forceinline__ uint32_t pack_bf16x2(float lo, float hi) {
    uint32_t d;
    asm("cvt.rn.bf16x2.f32 %0, %1, %2;" : "=r"(d) : "f"(hi), "f"(lo));
    return d;
}
// split a float pair into 3 bf16x2 levels
__device__ __forceinline__ void split_pair(float lo, float hi,
                                           uint32_t& h, uint32_t& m, uint32_t& l) {
    h = pack_bf16x2(lo, hi);
    float hlo = __uint_as_float(h << 16);
    float hhi = __uint_as_float(h & 0xffff0000u);
    float rlo = lo - hlo, rhi = hi - hhi;
    m = pack_bf16x2(rlo, rhi);
    float mlo = __uint_as_float(m << 16);
    float mhi = __uint_as_float(m & 0xffff0000u);
    l = pack_bf16x2(rlo - mlo, rhi - mhi);
}
__device__ __forceinline__ void lds128(uint32_t r[4], uint32_t addr) {
    asm volatile("ld.shared.v4.b32 {%0,%1,%2,%3}, [%4];"
                 : "=r"(r[0]), "=r"(r[1]), "=r"(r[2]), "=r"(r[3]) : "r"(addr));
}
__device__ __forceinline__ void lds64(uint32_t r[2], uint32_t addr) {
    asm volatile("ld.shared.v2.b32 {%0,%1}, [%2];"
                 : "=r"(r[0]), "=r"(r[1]) : "r"(addr));
}
__device__ __forceinline__ void mma_bf16(float c[4], const uint32_t a[4],
                                         uint32_t b0, uint32_t b1) {
    asm("mma.sync.aligned.m16n8k16.row.col.f32.bf16.bf16.f32 "
        "{%0,%1,%2,%3}, {%4,%5,%6,%7}, {%8,%9}, {%0,%1,%2,%3};"
        : "+f"(c[0]), "+f"(c[1]), "+f"(c[2]), "+f"(c[3])
        : "r"(a[0]), "r"(a[1]), "r"(a[2]), "r"(a[3]), "r"(b0), "r"(b1));
}

__global__ __launch_bounds__(TPB, 1)
void mlp_kernel(const float* __restrict__ x,
                const float* __restrict__ w1, const float* __restrict__ b1,
                const float* __restrict__ w2, const float* __restrict__ b2,
                const float* __restrict__ w3, const float* __restrict__ b3,
                float* __restrict__ out)
{
    extern __shared__ float sm[];
    char* smc = (char*)sm;
    float* sh1 = sm + H1_OFF_F;    // aliases the B region after the GEMM

    const int tid = threadIdx.x;
    const int wid = tid >> 5;
    const int lane = tid & 31;
    const int g = lane >> 2;       // 0..7
    const int tig = lane & 3;      // 0..3

    // ---- stage w1 as packed 3-level bf16 B-fragments ----
    // gmem col within k16-block: c = 4t + j; j in {0,1} -> reg b0 halves,
    // j in {2,3} -> reg b1 halves. cell = ((b*8+nt)*8+gg)*4+q, q=(t+gg)&3.
    // hm cell (16B): [h_b0, h_b1, m_b0, m_b1]; l cell (8B): [l_b0, l_b1].
    for (int e = tid; e < 16384; e += TPB) {
        int k = e >> 6, n = e & 63;
        float v = w1[e];
        __nv_bfloat16 hb = __float2bfloat16(v);
        float hf = __bfloat162float(hb);
        float r1 = v - hf;
        __nv_bfloat16 mb = __float2bfloat16(r1);
        float mf = __bfloat162float(mb);
        __nv_bfloat16 lb = __float2bfloat16(r1 - mf);
        int b = k >> 4, c = k & 15, t = c >> 2, j = c & 3;
        int nt = n >> 3, gg = n & 7;
        int q = (t + gg) & 3;
        uint32_t cell = (uint32_t)(((b * 8 + nt) * 8 + gg) * 4 + q);
        uint32_t sub = (uint32_t)((j >> 1) * 4 + (j & 1) * 2);
        *(__nv_bfloat16*)(smc + SBHM_OFF_B + cell * 16 + sub)     = hb;
        *(__nv_bfloat16*)(smc + SBHM_OFF_B + cell * 16 + 8 + sub) = mb;
        *(__nv_bfloat16*)(smc + SBL_OFF_B  + cell * 8  + sub)     = lb;
    }
    {
        float* sw2 = sm + W2_OFF_F;
        for (int i = tid; i < 1024; i += TPB) sw2[i] = w2[i];
        if (tid < 64) sm[B1_OFF_F + tid] = b1[tid];
        if (tid < 16) sm[B2_OFF_F + tid] = b2[tid];
        if (tid < 64) sm[W3_OFF_F + tid] = w3[tid];
        if (tid < 4)  sm[B3_OFF_F + tid] = b3[tid];
    }
    __syncthreads();

    const uint32_t smb = smem_u32(sm);
    const uint32_t hm_base = smb + SBHM_OFF_B + (uint32_t)((g * 4 + ((tig + g) & 3)) * 16);
    const uint32_t l_base  = smb + SBL_OFF_B  + (uint32_t)((g * 4 + ((tig + g) & 3)) * 8);

    // ---- layer-1 GEMM: warp computes rows [wid*32, wid*32+32), all 64 cols ----
    const float* xb = x + ((size_t)blockIdx.x * ROWS_CTA + wid * 32 + g) * KDIM + tig * 4;

    float c[2][8][4];
    #pragma unroll
    for (int mt = 0; mt < 2; mt++)
        #pragma unroll
        for (int nt = 0; nt < 8; nt++)
            #pragma unroll
            for (int r = 0; r < 4; r++) c[mt][nt][r] = 0.0f;

    // A: float4 per row per k16; cols 4tig..4tig+3 -> frag (a0.lo,a0.hi,a2.lo,a2.hi)
    float4 ra[2][2];   // [mt][row g / row g+8]
    #pragma unroll
    for (int mt = 0; mt < 2; mt++) {
        ra[mt][0] = __ldg((const float4*)(xb + mt * (16 * KDIM)));
        ra[mt][1] = __ldg((const float4*)(xb + mt * (16 * KDIM) + 8 * KDIM));
    }

    #pragma unroll 1
    for (int kt = 0; kt < 16; kt++) {
        // split current A into 3 levels (frees ra)
        uint32_t ah[2][4], am[2][4], al[2][4];
        #pragma unroll
        for (int mt = 0; mt < 2; mt++) {
            split_pair(ra[mt][0].x, ra[mt][0].y, ah[mt][0], am[mt][0], al[mt][0]); // a0: row g,  k lo
            split_pair(ra[mt][1].x, ra[mt][1].y, ah[mt][1], am[mt][1], al[mt][1]); // a1: row g+8
            split_pair(ra[mt][0].z, ra[mt][0].w, ah[mt][2], am[mt][2], al[mt][2]); // a2: row g,  k hi
            split_pair(ra[mt][1].z, ra[mt][1].w, ah[mt][3], am[mt][3], al[mt][3]); // a3
        }
        // prefetch next kt's A
        if (kt < 15) {
            #pragma unroll
            for (int mt = 0; mt < 2; mt++) {
                ra[mt][0] = __ldg((const float4*)(xb + mt * (16 * KDIM) + (kt + 1) * 16));
                ra[mt][1] = __ldg((const float4*)(xb + mt * (16 * KDIM) + 8 * KDIM + (kt + 1) * 16));
            }
        }

        const uint32_t hm_kt = hm_base + (uint32_t)(kt * 4096);  // nt stride 512B
        const uint32_t l_kt  = l_base  + (uint32_t)(kt * 2048);  // nt stride 256B

        #pragma unroll
        for (int ntp = 0; ntp < 4; ntp++) {
            const int n0 = 2 * ntp, n1 = 2 * ntp + 1;
            uint32_t v0[4], v1[4], l0[2], l1[2];
            lds128(v0, hm_kt + (uint32_t)(n0 * 512));
            lds128(v1, hm_kt + (uint32_t)(n1 * 512));
            lds64(l0, l_kt + (uint32_t)(n0 * 256));
            lds64(l1, l_kt + (uint32_t)(n1 * 256));

            // 6 terms, distance-4 accumulator reuse
            // hh
            mma_bf16(c[0][n0], ah[0], v0[0], v0[1]);
            mma_bf16(c[1][n0], ah[1], v0[0], v0[1]);
            mma_bf16(c[0][n1], ah[0], v1[0], v1[1]);
            mma_bf16(c[1][n1], ah[1], v1[0], v1[1]);
            // hm
            mma_bf16(c[0][n0], ah[0], v0[2], v0[3]);
            mma_bf16(c[1][n0], ah[1], v0[2], v0[3]);
            mma_bf16(c[0][n1], ah[0], v1[2], v1[3]);
            mma_bf16(c[1][n1], ah[1], v1[2], v1[3]);
            // mh
            mma_bf16(c[0][n0], am[0], v0[0], v0[1]);
            mma_bf16(c[1][n0], am[1], v0[0], v0[1]);
            mma_bf16(c[0][n1], am[0], v1[0], v1[1]);
            mma_bf16(c[1][n1], am[1], v1[0], v1[1]);
            // hl
            mma_bf16(c[0][n0], ah[0], l0[0], l0[1]);
            mma_bf16(c[1][n0], ah[1], l0[0], l0[1]);
            mma_bf16(c[0][n1], ah[0], l1[0], l1[1]);
            mma_bf16(c[1][n1], ah[1], l1[0], l1[1]);
            // mm
            mma_bf16(c[0][n0], am[0], v0[2], v0[3]);
            mma_bf16(c[1][n0], am[1], v0[2], v0[3]);
            mma_bf16(c[0][n1], am[0], v1[2], v1[3]);
            mma_bf16(c[1][n1], am[1], v1[2], v1[3]);
            // lh
            mma_bf16(c[0][n0], al[0], v0[0], v0[1]);
            mma_bf16(c[1][n0], al[1], v0[0], v0[1]);
            mma_bf16(c[0][n1], al[0], v1[0], v1[1]);
            mma_bf16(c[1][n1], al[1], v1[0], v1[1]);
        }
    }

    // ---- B region dead; alias with h1 and write C frags ----
    __syncthreads();
    #pragma unroll
    for (int mt = 0; mt < 2; mt++) {
        int row0 = wid * 32 + mt * 16 + g;
        #pragma unroll
        for (int nt = 0; nt < 8; nt++) {
            int col = nt * 8 + tig * 2;
            float2 v0; v0.x = c[mt][nt][0]; v0.y = c[mt][nt][1];
            float2 v1; v1.x = c[mt][nt][2]; v1.y = c[mt][nt][3];
            *(float2*)&sh1[row0 * H1_PITCH + col] = v0;
            *(float2*)&sh1[(row0 + 8) * H1_PITCH + col] = v1;
        }
    }
    __syncthreads();

    // ---- per-thread fp32 tail: row = tid ----
    const float* sb1 = sm + B1_OFF_F;
    const float* sw2 = sm + W2_OFF_F;
    const float* sb2 = sm + B2_OFF_F;
    const float* sw3 = sm + W3_OFF_F;
    const float* sb3 = sm + B3_OFF_F;
    const float* hrow = &sh1[tid * H1_PITCH];

    float h2[16];
    #pragma unroll
    for (int j = 0; j < 16; j++) h2[j] = sb2[j];
    #pragma unroll
    for (int i4 = 0; i4 < 16; i4++) {
        float4 hv = *(const float4*)&hrow[i4 * 4];
        float h0 = fmaxf(hv.x + sb1[i4 * 4 + 0], 0.0f);
        float h1v = fmaxf(hv.y + sb1[i4 * 4 + 1], 0.0f);
        float h2v = fmaxf(hv.z + sb1[i4 * 4 + 2], 0.0f);
        float h3 = fmaxf(hv.w + sb1[i4 * 4 + 3], 0.0f);
        const float* wr0 = &sw2[(i4 * 4 + 0) * 16];
        const float* wr1 = &sw2[(i4 * 4 + 1) * 16];
        const float* wr2 = &sw2[(i4 * 4 + 2) * 16];
        const float* wr3 = &sw2[(i4 * 4 + 3) * 16];
        #pragma unroll
        for (int j = 0; j < 16; j++) {
            float t = fmaf(h0, wr0[j], h2[j]);
            t = fmaf(h1v, wr1[j], t);
            t = fmaf(h2v, wr2[j], t);
            h2[j] = fmaf(h3, wr3[j], t);
        }
    }
    #pragma unroll
    for (int j = 0; j < 16; j++) h2[j] = tanhf(h2[j]);

    float lg[4];
    #pragma unroll
    for (int j = 0; j < 4; j++) lg[j] = sb3[j];
    #pragma unroll
    for (int i = 0; i < 16; i++) {
        float h = h2[i];
        const float* wr = &sw3[i * 4];
        #pragma unroll
        for (int j = 0; j < 4; j++) lg[j] = fmaf(h, wr[j], lg[j]);
    }

    float e0 = __expf(lg[0]);
    float e1 = __expf(lg[1]);
    float e2 = __expf(lg[2]);
    float e3 = __expf(lg[3]);

    const size_t row = (size_t)blockIdx.x * ROWS_CTA + tid;
    float4 ev; ev.x = e0; ev.y = e1; ev.z = e2; ev.w = e3;
    ((float4*)out)[row] = ev;

    // deterministic block partial sum
    float* red = sm + RED_OFF_F;
    red[tid] = (e0 + e1) + (e2 + e3);
    __syncthreads();
    #pragma unroll
    for (int off = TPB / 2; off > 0; off >>= 1) {
        if (tid < off) red[tid] += red[tid + off];
        __syncthreads();
    }
    if (tid == 0) g_partials[blockIdx.x] = red[0];
}

// fused: warp 0 deterministically reduces the 256 partials (identical order
// in every block -> identical result), broadcasts via smem, then scale.
__global__ void scale_kernel(float* __restrict__ out)
{
    __shared__ float sinv;
    const int tid = threadIdx.x;   // 256 threads
    if (tid < 32) {
        float s = 0.0f;
        #pragma unroll
        for (int i = 0; i < 8; i++) s += g_partials[tid * 8 + i];
        #pragma unroll
        for (int o = 16; o > 0; o >>= 1) s += __shfl_xor_sync(0xffffffffu, s, o);
        if (tid == 0) sinv = 1.0f / s;
    }
    __syncthreads();
    const float inv = sinv;

    const int i = blockIdx.x * blockDim.x + tid;  // one float4 per thread
    float4 v = ((float4*)out)[i];
    v.x *= inv; v.y *= inv; v.z *= inv; v.w *= inv;
    ((float4*)out)[i] = v;
}

extern "C" void kernel_launch(void* const* d_in, const int* in_sizes, int n_in,
                              void* d_out, int out_size)
{
    const float* x  = (const float*)d_in[0];
    const float* w1 = (const float*)d_in[1];
    const float* b1 = (const float*)d_in[2];
    const float* w2 = (const float*)d_in[3];
    const float* b2 = (const float*)d_in[4];
    const float* w3 = (const float*)d_in[5];
    const float* b3 = (const float*)d_in[6];
    float* out = (float*)d_out;

    const size_t smem = SM_FLOATS * sizeof(float);
    cudaFuncSetAttribute(mlp_kernel, cudaFuncAttributeMaxDynamicSharedMemorySize, (int)smem);

    mlp_kernel<<<NBLK, TPB, smem>>>(x, w1, b1, w2, b2, w3, b3, out);
    scale_kernel<<<(B_ROWS * 4) / (4 * 256), 256>>>(out);
}

// round 11
// speedup vs baseline: 1.4192x; 1.4192x over previous
#include <cuda_runtime.h>
#include <cuda_fp16.h>
#include <cstdint>

// EvroModel: x[131072,256] -> relu(x@w1+b1)[.,64] -> tanh(@w2+b2)[.,16] -> @w3+b3 [.,4]
// -> softmax over the ENTIRE flattened tensor.
//
// Round 11: layer-1 GEMM via 2-way fp16 split (x=xh+xl, w=wh+wl; 3 terms
// hh+hl+lh) on full-rate mma.sync.m16n8k16.f16 -> HALF the MMA count of the
// tf32/bf16 paths (768 vs 1536 per warp) at the same 2^-22 error level as
// the proven tf32 3-term kernel. One LDS.128 per (kt,nt) delivers BOTH
// weight levels. Epilogue/softmax unchanged.

#define B_ROWS   131072
#define ROWS_CTA 512
#define NBLK     (B_ROWS / ROWS_CTA)   // 256
#define TPB      512
#define KDIM     256
#define H1_PITCH 68

// byte offsets
#define SB_OFF_B   0                   // packed frags: 16kt*8nt*8g*4q cells *16B = 65536
// float offsets (h1 aliases the B region after the GEMM)
#define H1_OFF_F   0                   // 512 x 68 floats = 139264 B
#define W2_OFF_F   34816               // 64 x 16
#define B1_OFF_F   35840               // 64
#define B2_OFF_F   35904               // 16
#define W3_OFF_F   35920               // 16 x 4
#define B3_OFF_F   35984               // 4
#define RED_OFF_F  35988               // 512
#define SM_FLOATS  36500

__device__ float g_partials[NBLK];

__device__ __forceinline__ uint32_t smem_u32(const void* p) {
    uint32_t a;
    asm("{ .reg .u64 t; cvta.to.shared.u64 t, %1; cvt.u32.u64 %0, t; }" : "=r"(a) : "l"(p));
    return a;
}
// pack two floats into f16x2: lower half = lo, upper half = hi
__device__ __forceinline__ uint32_t pack_f16x2(float lo, float hi) {
    uint32_t d;
    asm("cvt.rn.f16x2.f32 %0, %1, %2;" : "=r"(d) : "f"(hi), "f"(lo));
    return d;
}
__device__ __forceinline__ void unpack_f16x2(uint32_t h, float& lo, float& hi) {
    asm("{ .reg .f16 x, y; mov.b32 {x, y}, %2; cvt.f32.f16 %0, x; cvt.f32.f16 %1, y; }"
        : "=f"(lo), "=f"(hi) : "r"(h));
}
// split a float pair into 2 fp16x2 levels (h + l, residual exact in fp32)
__device__ __forceinline__ void split_pair(float lo, float hi, uint32_t& h, uint32_t& l) {
    h = pack_f16x2(lo, hi);
    float hlo, hhi;
    unpack_f16x2(h, hlo, hhi);
    l = pack_f16x2(lo - hlo, hi - hhi);
}
__device__ __forceinline__ void lds128(uint32_t r[4], uint32_t addr) {
    asm volatile("ld.shared.v4.b32 {%0,%1,%2,%3}, [%4];"
                 : "=r"(r[0]), "=r"(r[1]), "=r"(r[2]), "=r"(r[3]) : "r"(addr));
}
__device__ __forceinline__ void mma_f16(float c[4], const uint32_t a[4],
                                        uint32_t b0, uint32_t b1) {
    asm("mma.sync.aligned.m16n8k16.row.col.f32.f16.f16.f32 "
        "{%0,%1,%2,%3}, {%4,%5,%6,%7}, {%8,%9}, {%0,%1,%2,%3};"
        : "+f"(c[0]), "+f"(c[1]), "+f"(c[2]), "+f"(c[3])
        : "r"(a[0]), "r"(a[1]), "r"(a[2]), "r"(a[3]), "r"(b0), "r"(b1));
}

__global__ __launch_bounds__(TPB, 1)
void mlp_kernel(const float* __restrict__ x,
                const float* __restrict__ w1, const float* __restrict__ b1,
                const float* __restrict__ w2, const float* __restrict__ b2,
                const float* __restrict__ w3, const float* __restrict__ b3,
                float* __restrict__ out)
{
    extern __shared__ float sm[];
    char* smc = (char*)sm;
    float* sh1 = sm + H1_OFF_F;    // aliases the B region after the GEMM

    const int tid = threadIdx.x;
    const int wid = tid >> 5;
    const int lane = tid & 31;
    const int g = lane >> 2;       // 0..7
    const int tig = lane & 3;      // 0..3

    // ---- stage w1 as packed 2-level fp16 B-fragments ----
    // w1[k][n]: b=k>>4 (kt16), c=k&15, t=c>>2, j=c&3.
    // cell = ((b*8+nt)*8+gg)*4+q, q=(t+gg)&3, 16B = [h_b0, h_b1, l_b0, l_b1].
    // within-half byte: sub = (j>>1)*4 + (j&1)*2; l at sub+8.
    for (int e = tid; e < 16384; e += TPB) {
        int k = e >> 6, n = e & 63;
        float v = w1[e];
        __half hb = __float2half_rn(v);
        float hf = __half2float(hb);
        __half lb = __float2half_rn(v - hf);
        int b = k >> 4, c = k & 15, t = c >> 2, j = c & 3;
        int nt = n >> 3, gg = n & 7;
        int q = (t + gg) & 3;
        uint32_t cell = (uint32_t)(((b * 8 + nt) * 8 + gg) * 4 + q);
        uint32_t sub = (uint32_t)((j >> 1) * 4 + (j & 1) * 2);
        *(__half*)(smc + SB_OFF_B + cell * 16 + sub)     = hb;
        *(__half*)(smc + SB_OFF_B + cell * 16 + 8 + sub) = lb;
    }
    {
        float* sw2 = sm + W2_OFF_F;
        for (int i = tid; i < 1024; i += TPB) sw2[i] = w2[i];
        if (tid < 64) sm[B1_OFF_F + tid] = b1[tid];
        if (tid < 16) sm[B2_OFF_F + tid] = b2[tid];
        if (tid < 64) sm[W3_OFF_F + tid] = w3[tid];
        if (tid < 4)  sm[B3_OFF_F + tid] = b3[tid];
    }
    __syncthreads();

    const uint32_t smb = smem_u32(sm);
    const uint32_t b_base = smb + SB_OFF_B + (uint32_t)((g * 4 + ((tig + g) & 3)) * 16);

    // ---- layer-1 GEMM: warp computes rows [wid*32, wid*32+32), all 64 cols ----
    const float* xb = x + ((size_t)blockIdx.x * ROWS_CTA + wid * 32 + g) * KDIM + tig * 4;

    float c[2][8][4];
    #pragma unroll
    for (int mt = 0; mt < 2; mt++)
        #pragma unroll
        for (int nt = 0; nt < 8; nt++)
            #pragma unroll
            for (int r = 0; r < 4; r++) c[mt][nt][r] = 0.0f;

    // A: float4 per row per k16; gmem cols 4tig..4tig+3 -> frag halves
    // (a0.lo, a0.hi, a2.lo, a2.hi) under the k-permutation shared with B.
    float4 ra[2][2];   // [mt][row g / row g+8]
    #pragma unroll
    for (int mt = 0; mt < 2; mt++) {
        ra[mt][0] = __ldg((const float4*)(xb + mt * (16 * KDIM)));
        ra[mt][1] = __ldg((const float4*)(xb + mt * (16 * KDIM) + 8 * KDIM));
    }

    #pragma unroll 1
    for (int kt = 0; kt < 16; kt++) {
        // split current A into 2 fp16 levels
        uint32_t ah[2][4], al[2][4];
        #pragma unroll
        for (int mt = 0; mt < 2; mt++) {
            split_pair(ra[mt][0].x, ra[mt][0].y, ah[mt][0], al[mt][0]); // a0: row g,  k lo-pair
            split_pair(ra[mt][1].x, ra[mt][1].y, ah[mt][1], al[mt][1]); // a1: row g+8
            split_pair(ra[mt][0].z, ra[mt][0].w, ah[mt][2], al[mt][2]); // a2: row g,  k hi-pair
            split_pair(ra[mt][1].z, ra[mt][1].w, ah[mt][3], al[mt][3]); // a3
        }
        // prefetch next kt's A
        if (kt < 15) {
            #pragma unroll
            for (int mt = 0; mt < 2; mt++) {
                ra[mt][0] = __ldg((const float4*)(xb + mt * (16 * KDIM) + (kt + 1) * 16));
                ra[mt][1] = __ldg((const float4*)(xb + mt * (16 * KDIM) + 8 * KDIM + (kt + 1) * 16));
            }
        }

        const uint32_t kt_base = b_base + (uint32_t)(kt * 4096);  // nt stride 512B

        #pragma unroll
        for (int ntp = 0; ntp < 4; ntp++) {
            const int n0 = 2 * ntp, n1 = 2 * ntp + 1;
            uint32_t v0[4], v1[4];
            lds128(v0, kt_base + (uint32_t)(n0 * 512));   // [h_b0,h_b1,l_b0,l_b1]
            lds128(v1, kt_base + (uint32_t)(n1 * 512));

            // 3 terms, distance-4 accumulator reuse
            // hh
            mma_f16(c[0][n0], ah[0], v0[0], v0[1]);
            mma_f16(c[1][n0], ah[1], v0[0], v0[1]);
            mma_f16(c[0][n1], ah[0], v1[0], v1[1]);
            mma_f16(c[1][n1], ah[1], v1[0], v1[1]);
            // hl (xh * wl)
            mma_f16(c[0][n0], ah[0], v0[2], v0[3]);
            mma_f16(c[1][n0], ah[1], v0[2], v0[3]);
            mma_f16(c[0][n1], ah[0], v1[2], v1[3]);
            mma_f16(c[1][n1], ah[1], v1[2], v1[3]);
            // lh (xl * wh)
            mma_f16(c[0][n0], al[0], v0[0], v0[1]);
            mma_f16(c[1][n0], al[1], v0[0], v0[1]);
            mma_f16(c[0][n1], al[0], v1[0], v1[1]);
            mma_f16(c[1][n1], al[1], v1[0], v1[1]);
        }
    }

    // ---- B region dead; alias with h1 and write C frags ----
    __syncthreads();
    #pragma unroll
    for (int mt = 0; mt < 2; mt++) {
        int row0 = wid * 32 + mt * 16 + g;
        #pragma unroll
        for (int nt = 0; nt < 8; nt++) {
            int col = nt * 8 + tig * 2;
            float2 v0; v0.x = c[mt][nt][0]; v0.y = c[mt][nt][1];
            float2 v1; v1.x = c[mt][nt][2]; v1.y = c[mt][nt][3];
            *(float2*)&sh1[row0 * H1_PITCH + col] = v0;
            *(float2*)&sh1[(row0 + 8) * H1_PITCH + col] = v1;
        }
    }
    __syncthreads();

    // ---- per-thread fp32 tail: row = tid ----
    const float* sb1 = sm + B1_OFF_F;
    const float* sw2 = sm + W2_OFF_F;
    const float* sb2 = sm + B2_OFF_F;
    const float* sw3 = sm + W3_OFF_F;
    const float* sb3 = sm + B3_OFF_F;
    const float* hrow = &sh1[tid * H1_PITCH];

    float h2[16];
    #pragma unroll
    for (int j = 0; j < 16; j++) h2[j] = sb2[j];
    #pragma unroll
    for (int i4 = 0; i4 < 16; i4++) {
        float4 hv = *(const float4*)&hrow[i4 * 4];
        float h0 = fmaxf(hv.x + sb1[i4 * 4 + 0], 0.0f);
        float h1v = fmaxf(hv.y + sb1[i4 * 4 + 1], 0.0f);
        float h2v = fmaxf(hv.z + sb1[i4 * 4 + 2], 0.0f);
        float h3 = fmaxf(hv.w + sb1[i4 * 4 + 3], 0.0f);
        const float* wr0 = &sw2[(i4 * 4 + 0) * 16];
        const float* wr1 = &sw2[(i4 * 4 + 1) * 16];
        const float* wr2 = &sw2[(i4 * 4 + 2) * 16];
        const float* wr3 = &sw2[(i4 * 4 + 3) * 16];
        #pragma unroll
        for (int j = 0; j < 16; j++) {
            float t = fmaf(h0, wr0[j], h2[j]);
            t = fmaf(h1v, wr1[j], t);
            t = fmaf(h2v, wr2[j], t);
            h2[j] = fmaf(h3, wr3[j], t);
        }
    }
    #pragma unroll
    for (int j = 0; j < 16; j++) h2[j] = tanhf(h2[j]);

    float lg[4];
    #pragma unroll
    for (int j = 0; j < 4; j++) lg[j] = sb3[j];
    #pragma unroll
    for (int i = 0; i < 16; i++) {
        float h = h2[i];
        const float* wr = &sw3[i * 4];
        #pragma unroll
        for (int j = 0; j < 4; j++) lg[j] = fmaf(h, wr[j], lg[j]);
    }

    float e0 = __expf(lg[0]);
    float e1 = __expf(lg[1]);
    float e2 = __expf(lg[2]);
    float e3 = __expf(lg[3]);

    const size_t row = (size_t)blockIdx.x * ROWS_CTA + tid;
    float4 ev; ev.x = e0; ev.y = e1; ev.z = e2; ev.w = e3;
    ((float4*)out)[row] = ev;

    // deterministic block partial sum
    float* red = sm + RED_OFF_F;
    red[tid] = (e0 + e1) + (e2 + e3);
    __syncthreads();
    #pragma unroll
    for (int off = TPB / 2; off > 0; off >>= 1) {
        if (tid < off) red[tid] += red[tid + off];
        __syncthreads();
    }
    if (tid == 0) g_partials[blockIdx.x] = red[0];
}

// fused: warp 0 deterministically reduces the 256 partials (identical order
// in every block -> identical result), broadcasts via smem, then scale.
__global__ void scale_kernel(float* __restrict__ out)
{
    __shared__ float sinv;
    const int tid = threadIdx.x;   // 256 threads
    if (tid < 32) {
        float s = 0.0f;
        #pragma unroll
        for (int i = 0; i < 8; i++) s += g_partials[tid * 8 + i];
        #pragma unroll
        for (int o = 16; o > 0; o >>= 1) s += __shfl_xor_sync(0xffffffffu, s, o);
        if (tid == 0) sinv = 1.0f / s;
    }
    __syncthreads();
    const float inv = sinv;

    const int i = blockIdx.x * blockDim.x + tid;  // one float4 per thread
    float4 v = ((float4*)out)[i];
    v.x *= inv; v.y *= inv; v.z *= inv; v.w *= inv;
    ((float4*)out)[i] = v;
}

extern "C" void kernel_launch(void* const* d_in, const int* in_sizes, int n_in,
                              void* d_out, int out_size)
{
    const float* x  = (const float*)d_in[0];
    const float* w1 = (const float*)d_in[1];
    const float* b1 = (const float*)d_in[2];
    const float* w2 = (const float*)d_in[3];
    const float* b2 = (const float*)d_in[4];
    const float* w3 = (const float*)d_in[5];
    const float* b3 = (const float*)d_in[6];
    float* out = (float*)d_out;

    const size_t smem = SM_FLOATS * sizeof(float);
    cudaFuncSetAttribute(mlp_kernel, cudaFuncAttributeMaxDynamicSharedMemorySize, (int)smem);

    mlp_kernel<<<NBLK, TPB, smem>>>(x, w1, b1, w2, b2, w3, b3, out);
    scale_kernel<<<(B_ROWS * 4) / (4 * 256), 256>>>(out);
}